// round 3
// baseline (speedup 1.0000x reference)
#include <cuda_runtime.h>
#include <math.h>

#define NROWS 65536
#define K1 512
#define A3C 64
#define CW 16
#define DT 8
#define PPC 96

// ---------------- scratch (device globals; no runtime allocation) -------------
__device__ float g_t[(size_t)NROWS * A3C];            // normalized t        16 MB
__device__ float g_h[(size_t)DT * NROWS * A3C];       // tower pre-BN h     134 MB
__device__ float g_y[(size_t)DT * NROWS * PPC];       // tower outputs      201 MB
__device__ float g_ps[(size_t)DT * A3C * 512];        // partial sums
__device__ float g_pq[(size_t)DT * A3C * 512];        // partial sumsq
__device__ float g_scale[DT * A3C];                   // rsig*gamma
__device__ float g_shift[DT * A3C];                   // beta - mu*scale

// ---------------- kernel 1: t = normalize(x @ B) ------------------------------
// block: 256 thr, tile 128 rows x 64 cols, K-tiles of 32. reg tile 4x8.
__global__ __launch_bounds__(256) void k1_gemm_norm(const float* __restrict__ x,
                                                    const float* __restrict__ B) {
    __shared__ float Xs[32 * 129];   // k-major, padded
    __shared__ float Bs[32 * 64];
    __shared__ float invs[128];
    int tid = threadIdx.x;
    int tx = tid & 7, ty = tid >> 3;          // tx: 8 col-groups of 8, ty: 32 row-groups of 4
    int n0 = blockIdx.x * 128;

    float acc[4][8];
#pragma unroll
    for (int j = 0; j < 4; j++)
#pragma unroll
        for (int c = 0; c < 8; c++) acc[j][c] = 0.f;

    for (int kt = 0; kt < 16; kt++) {
        int k0 = kt * 32;
#pragma unroll
        for (int i = 0; i < 4; i++) {
            int l = tid + i * 256;            // 0..1023
            int r = l >> 3, kk4 = l & 7;
            float4 v = *(const float4*)(x + (size_t)(n0 + r) * K1 + k0 + kk4 * 4);
            Xs[(kk4 * 4 + 0) * 129 + r] = v.x;
            Xs[(kk4 * 4 + 1) * 129 + r] = v.y;
            Xs[(kk4 * 4 + 2) * 129 + r] = v.z;
            Xs[(kk4 * 4 + 3) * 129 + r] = v.w;
        }
#pragma unroll
        for (int i = 0; i < 2; i++) {
            int l = tid + i * 256;            // 0..511
            int kk = l >> 4, c4 = l & 15;
            *(float4*)(Bs + kk * 64 + c4 * 4) =
                *(const float4*)(B + (size_t)(k0 + kk) * 64 + c4 * 4);
        }
        __syncthreads();
#pragma unroll
        for (int kk = 0; kk < 32; kk++) {
            float ar[4];
#pragma unroll
            for (int j = 0; j < 4; j++) ar[j] = Xs[kk * 129 + ty * 4 + j];
            float4 b0 = *(const float4*)(Bs + kk * 64 + tx * 8);
            float4 b1 = *(const float4*)(Bs + kk * 64 + tx * 8 + 4);
#pragma unroll
            for (int j = 0; j < 4; j++) {
                acc[j][0] += ar[j] * b0.x; acc[j][1] += ar[j] * b0.y;
                acc[j][2] += ar[j] * b0.z; acc[j][3] += ar[j] * b0.w;
                acc[j][4] += ar[j] * b1.x; acc[j][5] += ar[j] * b1.y;
                acc[j][6] += ar[j] * b1.z; acc[j][7] += ar[j] * b1.w;
            }
        }
        __syncthreads();
    }
    // row L2-norm reduce across the 8 tx groups (reuse Bs)
    float* ps = Bs;
#pragma unroll
    for (int j = 0; j < 4; j++) {
        float s = 0.f;
#pragma unroll
        for (int c = 0; c < 8; c++) s += acc[j][c] * acc[j][c];
        ps[(ty * 4 + j) * 8 + tx] = s;
    }
    __syncthreads();
    if (tid < 128) {
        float s = 0.f;
#pragma unroll
        for (int q = 0; q < 8; q++) s += ps[tid * 8 + q];
        float nrm = sqrtf(s);
        invs[tid] = 1.f / fmaxf(nrm, 1e-12f);
    }
    __syncthreads();
#pragma unroll
    for (int j = 0; j < 4; j++) {
        int r = ty * 4 + j;
        float inv = invs[r];
        float4 o0, o1;
        o0.x = acc[j][0] * inv; o0.y = acc[j][1] * inv; o0.z = acc[j][2] * inv; o0.w = acc[j][3] * inv;
        o1.x = acc[j][4] * inv; o1.y = acc[j][5] * inv; o1.z = acc[j][6] * inv; o1.w = acc[j][7] * inv;
        *(float4*)(g_t + (size_t)(n0 + r) * 64 + tx * 8)     = o0;
        *(float4*)(g_t + (size_t)(n0 + r) * 64 + tx * 8 + 4) = o1;
    }
}

// ---------------- kernel 2: windowed affine sum -> rep -----------------------
__global__ __launch_bounds__(256) void k2_window(const float* __restrict__ lw,
                                                 const float* __restrict__ lb,
                                                 float* __restrict__ rep) {
    __shared__ float ts[143 * 64];
    int tid = threadIdx.x;
    int a = tid & 63, rg = tid >> 6;          // a: feature, rg: 0..3
    int R0 = blockIdx.x * 128;

    for (int l = tid; l < 143 * 64; l += 256) {
        int s = l >> 6, aa = l & 63;
        int g = R0 - 15 + s;
        ts[l] = (g >= 0) ? g_t[(size_t)g * 64 + aa] : 0.f;
    }
    float w[CW];
    float bs = 0.f;
#pragma unroll
    for (int j = 0; j < CW; j++) { w[j] = lw[j * 64 + a]; bs += lb[j * 64 + a]; }
    __syncthreads();

    for (int m = 0; m < 32; m++) {
        int r = m * 4 + rg;
        int i = R0 + r;
        float acc = bs;
        if (i >= CW - 1) {
#pragma unroll
            for (int j = 0; j < CW; j++) acc += w[j] * ts[(r + j) * 64 + a];
        } else {
#pragma unroll
            for (int j = 0; j < CW; j++) {
                int g = min(j, i);
                acc += w[j] * ts[(g + 15) * 64 + a];
            }
        }
        rep[(size_t)i * 64 + a] = acc;
    }
}

// ---------------- kernel 3: h[d] = rep @ W1[d] + b1[d], + BN partials --------
__global__ __launch_bounds__(256) void k3_gemm_h(const float* __restrict__ rep,
                                                 const float* __restrict__ W1,
                                                 const float* __restrict__ b1) {
    __shared__ float Rs[32 * 129];
    __shared__ float Ws[64 * 64];
    int tid = threadIdx.x;
    int tx = tid & 7, ty = tid >> 3;
    int d = blockIdx.y;
    int n0 = blockIdx.x * 128;

#pragma unroll
    for (int i = 0; i < 4; i++) {
        int l = tid + i * 256;
        *(float4*)(Ws + l * 4) = *(const float4*)(W1 + (size_t)d * 4096 + l * 4);
    }
    float acc[4][8];
#pragma unroll
    for (int j = 0; j < 4; j++)
#pragma unroll
        for (int c = 0; c < 8; c++) acc[j][c] = 0.f;

    for (int kt = 0; kt < 2; kt++) {
        int k0 = kt * 32;
#pragma unroll
        for (int i = 0; i < 4; i++) {
            int l = tid + i * 256;
            int r = l >> 3, kk4 = l & 7;
            float4 v = *(const float4*)(rep + (size_t)(n0 + r) * 64 + k0 + kk4 * 4);
            Rs[(kk4 * 4 + 0) * 129 + r] = v.x;
            Rs[(kk4 * 4 + 1) * 129 + r] = v.y;
            Rs[(kk4 * 4 + 2) * 129 + r] = v.z;
            Rs[(kk4 * 4 + 3) * 129 + r] = v.w;
        }
        __syncthreads();
#pragma unroll
        for (int kk = 0; kk < 32; kk++) {
            float ar[4];
#pragma unroll
            for (int j = 0; j < 4; j++) ar[j] = Rs[kk * 129 + ty * 4 + j];
            float4 b0 = *(const float4*)(Ws + (k0 + kk) * 64 + tx * 8);
            float4 b1v = *(const float4*)(Ws + (k0 + kk) * 64 + tx * 8 + 4);
#pragma unroll
            for (int j = 0; j < 4; j++) {
                acc[j][0] += ar[j] * b0.x;  acc[j][1] += ar[j] * b0.y;
                acc[j][2] += ar[j] * b0.z;  acc[j][3] += ar[j] * b0.w;
                acc[j][4] += ar[j] * b1v.x; acc[j][5] += ar[j] * b1v.y;
                acc[j][6] += ar[j] * b1v.z; acc[j][7] += ar[j] * b1v.w;
            }
        }
        __syncthreads();
    }
    // epilogue: +b1, write h, BN partial sums
    float bb[8];
#pragma unroll
    for (int c = 0; c < 8; c++) bb[c] = b1[d * 64 + tx * 8 + c];
    float s[8], q[8];
#pragma unroll
    for (int c = 0; c < 8; c++) { s[c] = 0.f; q[c] = 0.f; }
#pragma unroll
    for (int j = 0; j < 4; j++) {
        int r = ty * 4 + j;
        float4 o0, o1;
        float v0 = acc[j][0] + bb[0], v1 = acc[j][1] + bb[1], v2 = acc[j][2] + bb[2], v3 = acc[j][3] + bb[3];
        float v4 = acc[j][4] + bb[4], v5 = acc[j][5] + bb[5], v6 = acc[j][6] + bb[6], v7 = acc[j][7] + bb[7];
        s[0] += v0; s[1] += v1; s[2] += v2; s[3] += v3; s[4] += v4; s[5] += v5; s[6] += v6; s[7] += v7;
        q[0] += v0*v0; q[1] += v1*v1; q[2] += v2*v2; q[3] += v3*v3;
        q[4] += v4*v4; q[5] += v5*v5; q[6] += v6*v6; q[7] += v7*v7;
        o0.x = v0; o0.y = v1; o0.z = v2; o0.w = v3;
        o1.x = v4; o1.y = v5; o1.z = v6; o1.w = v7;
        float* hp = g_h + (size_t)d * NROWS * 64 + (size_t)(n0 + r) * 64 + tx * 8;
        *(float4*)(hp) = o0;
        *(float4*)(hp + 4) = o1;
    }
    float* psum = Rs;            // 2048 floats
    float* psq  = Rs + 2048;     // 2048 floats (Rs has 4128)
#pragma unroll
    for (int c = 0; c < 8; c++) {
        psum[ty * 64 + tx * 8 + c] = s[c];
        psq [ty * 64 + tx * 8 + c] = q[c];
    }
    __syncthreads();
    if (tid < 64) {
        float S = 0.f, Q = 0.f;
#pragma unroll
        for (int t2 = 0; t2 < 32; t2++) { S += psum[t2 * 64 + tid]; Q += psq[t2 * 64 + tid]; }
        g_ps[((size_t)d * 64 + tid) * 512 + blockIdx.x] = S;
        g_pq[((size_t)d * 64 + tid) * 512 + blockIdx.x] = Q;
    }
}

// ---------------- kernel 4: deterministic BN stats reduce --------------------
__global__ __launch_bounds__(128) void k4_stats(const float* __restrict__ gamma,
                                                const float* __restrict__ beta) {
    int id = blockIdx.x;            // d*64 + c
    int tid = threadIdx.x;
    float S = 0.f, Q = 0.f;
    for (int i = tid; i < 512; i += 128) {
        S += g_ps[(size_t)id * 512 + i];
        Q += g_pq[(size_t)id * 512 + i];
    }
    __shared__ float ss[128], qq[128];
    ss[tid] = S; qq[tid] = Q;
    __syncthreads();
    for (int off = 64; off > 0; off >>= 1) {
        if (tid < off) { ss[tid] += ss[tid + off]; qq[tid] += qq[tid + off]; }
        __syncthreads();
    }
    if (tid == 0) {
        float mu  = ss[0] * (1.f / 65536.f);
        float var = qq[0] * (1.f / 65536.f) - mu * mu;
        float rs  = rsqrtf(fmaxf(var, 0.f) + 1e-5f);
        float sc  = rs * gamma[id];
        g_scale[id] = sc;
        g_shift[id] = beta[id] - mu * sc;
    }
}

// ---------------- kernel 5: BN+ELU then y[d] = h' @ W2[d] + b2[d] ------------
__global__ __launch_bounds__(256) void k5_bn_gemm2(const float* __restrict__ W2,
                                                   const float* __restrict__ b2) {
    __shared__ float Hs[32 * 129];
    __shared__ float Ws[64 * 96];
    __shared__ float sA[64], sB[64];
    int tid = threadIdx.x;
    int tx = tid & 15, ty = tid >> 4;   // tx: 16 col-groups of 6, ty: 16 row-groups of 8
    int d = blockIdx.y;
    int n0 = blockIdx.x * 128;

    if (tid < 64) { sA[tid] = g_scale[d * 64 + tid]; sB[tid] = g_shift[d * 64 + tid]; }
#pragma unroll
    for (int i = 0; i < 6; i++) {
        int l = tid + i * 256;
        *(float4*)(Ws + l * 4) = *(const float4*)(W2 + (size_t)d * 6144 + l * 4);
    }
    float acc[8][6];
#pragma unroll
    for (int j = 0; j < 8; j++)
#pragma unroll
        for (int c = 0; c < 6; c++) acc[j][c] = 0.f;
    __syncthreads();

    for (int kt = 0; kt < 2; kt++) {
        int k0 = kt * 32;
#pragma unroll
        for (int i = 0; i < 4; i++) {
            int l = tid + i * 256;
            int r = l >> 3, kk4 = l & 7;
            float4 v = *(const float4*)(g_h + (size_t)d * NROWS * 64 +
                                        (size_t)(n0 + r) * 64 + k0 + kk4 * 4);
            int b0 = k0 + kk4 * 4;
            float e;
            e = v.x * sA[b0 + 0] + sB[b0 + 0]; e = e > 0.f ? e : expm1f(e); Hs[(kk4*4+0)*129 + r] = e;
            e = v.y * sA[b0 + 1] + sB[b0 + 1]; e = e > 0.f ? e : expm1f(e); Hs[(kk4*4+1)*129 + r] = e;
            e = v.z * sA[b0 + 2] + sB[b0 + 2]; e = e > 0.f ? e : expm1f(e); Hs[(kk4*4+2)*129 + r] = e;
            e = v.w * sA[b0 + 3] + sB[b0 + 3]; e = e > 0.f ? e : expm1f(e); Hs[(kk4*4+3)*129 + r] = e;
        }
        __syncthreads();
#pragma unroll
        for (int kk = 0; kk < 32; kk++) {
            float ar[8];
#pragma unroll
            for (int j = 0; j < 8; j++) ar[j] = Hs[kk * 129 + ty * 8 + j];
            const float* wp = Ws + (k0 + kk) * 96 + tx * 6;
            float2 w0 = *(const float2*)(wp);
            float2 w1 = *(const float2*)(wp + 2);
            float2 w2 = *(const float2*)(wp + 4);
#pragma unroll
            for (int j = 0; j < 8; j++) {
                acc[j][0] += ar[j] * w0.x; acc[j][1] += ar[j] * w0.y;
                acc[j][2] += ar[j] * w1.x; acc[j][3] += ar[j] * w1.y;
                acc[j][4] += ar[j] * w2.x; acc[j][5] += ar[j] * w2.y;
            }
        }
        __syncthreads();
    }
    float bb[6];
#pragma unroll
    for (int c = 0; c < 6; c++) bb[c] = b2[d * 96 + tx * 6 + c];
#pragma unroll
    for (int j = 0; j < 8; j++) {
        int r = ty * 8 + j;
        float* op = g_y + (size_t)d * NROWS * 96 + (size_t)(n0 + r) * 96 + tx * 6;
        float2 o;
        o.x = acc[j][0] + bb[0]; o.y = acc[j][1] + bb[1]; *(float2*)(op)     = o;
        o.x = acc[j][2] + bb[2]; o.y = acc[j][3] + bb[3]; *(float2*)(op + 2) = o;
        o.x = acc[j][4] + bb[4]; o.y = acc[j][5] + bb[5]; *(float2*)(op + 4) = o;
    }
}

// ---------------- kernel 6: interleave y[d][n][p] -> y_1[n][p*8+d] -----------
// plane stride 772 => bank index (4d+p) mod 32: all 32 lanes distinct, conflict-free.
__global__ __launch_bounds__(256) void k6_interleave(float* __restrict__ out) {
    __shared__ float sm[8 * 772];
    int tid = threadIdx.x;
    int n0 = blockIdx.x * 8;
#pragma unroll
    for (int i = 0; i < 24; i++) {
        int l = tid + i * 256;              // 0..6143
        int d = l / 768; int m = l % 768; int n = m / 96; int p = m % 96;
        sm[d * 772 + n * 96 + p] = g_y[(size_t)d * NROWS * 96 + (size_t)(n0 + n) * 96 + p];
    }
    __syncthreads();
#pragma unroll
    for (int i = 0; i < 24; i++) {
        int l = tid + i * 256;
        int n = l / 768; int q = l % 768; int p = q >> 3; int dd = q & 7;
        out[(size_t)(n0 + n) * 768 + q] = sm[dd * 772 + n * 96 + p];
    }
}

// ---------------- launcher ----------------------------------------------------
extern "C" void kernel_launch(void* const* d_in, const int* in_sizes, int n_in,
                              void* d_out, int out_size) {
    const float* x     = (const float*)d_in[0];
    const float* B     = (const float*)d_in[1];
    const float* lw    = (const float*)d_in[2];
    const float* lb    = (const float*)d_in[3];
    const float* W1    = (const float*)d_in[4];
    const float* b1    = (const float*)d_in[5];
    const float* gamma = (const float*)d_in[6];
    const float* beta  = (const float*)d_in[7];
    const float* W2    = (const float*)d_in[8];
    const float* b2    = (const float*)d_in[9];
    // flag (d_in[10]) == 1 and label unused in forward; shapes fix the flag=1 path.

    float* out = (float*)d_out;
    float* rep = out + (size_t)NROWS * (PPC * DT);   // rep section after y_1

    k1_gemm_norm<<<512, 256>>>(x, B);
    k2_window<<<512, 256>>>(lw, lb, rep);
    k3_gemm_h<<<dim3(512, 8), 256>>>(rep, W1, b1);
    k4_stats<<<512, 128>>>(gamma, beta);
    k5_bn_gemm2<<<dim3(512, 8), 256>>>(W2, b2);
    k6_interleave<<<8192, 256>>>(out);
}